// round 14
// baseline (speedup 1.0000x reference)
#include <cuda_runtime.h>
#include <math.h>
#include <stdint.h>

#define NN 65536
#define GG 128
#define LL 512
#define DD 128
#define EE 262144
#define NSTEPS 6
#define CC 256
#define L1OUT 510   // conv K=3 valid out length
#define P1OUT 254   // pool (3,2) out
#define P2OUT 127   // pool (2,2) out

// ---------------- scratch (device globals; no allocs allowed) ----------------
__device__ float g_h[NN * DD];
__device__ float g_m[NN * DD];
__device__ float g_agg[NN * DD];
__device__ float g_gx[NN * 3 * DD];
__device__ float g_gh[NN * 3 * DD];
__device__ float g_c[NN * CC];
__device__ float g_wT[NSTEPS * DD * DD];
__device__ float g_w1p[3 * DD * DD];
__device__ float g_wc1p[3 * CC * CC];
__device__ float g_convY1[NN * DD];            // [G,512,D] padded length
__device__ float g_poolY1[GG * P1OUT * DD];
__device__ float g_convY2[GG * P1OUT * DD];
__device__ float g_poolY2[GG * P2OUT * DD];
__device__ float g_convZ1[NN * CC];            // [G,512,C] padded length
__device__ float g_poolZ1[GG * P1OUT * CC];
__device__ float g_convZ2[GG * P1OUT * CC];
__device__ float g_poolZ2[GG * P2OUT * CC];
__device__ float g_stats[512];                 // per-channel sum / sumsq

// ---------------- bf16 helpers ----------------
// pack two floats as bf16x2: low half = lo_src, high half = hi_src
__device__ __forceinline__ unsigned bfpack(float hi_src, float lo_src) {
    unsigned r;
    asm("cvt.rn.bf16x2.f32 %0, %1, %2;" : "=r"(r) : "f"(hi_src), "f"(lo_src));
    return r;
}

__device__ __forceinline__ void mma_bf16(float* d, const unsigned* a, const unsigned* b) {
    asm("mma.sync.aligned.m16n8k16.row.col.f32.bf16.bf16.f32 "
        "{%0,%1,%2,%3}, {%4,%5,%6,%7}, {%8,%9}, {%0,%1,%2,%3};"
        : "+f"(d[0]), "+f"(d[1]), "+f"(d[2]), "+f"(d[3])
        : "r"(a[0]), "r"(a[1]), "r"(a[2]), "r"(a[3]), "r"(b[0]), "r"(b[1]));
}

// ---------------- small utility kernels ----------------
__global__ void fill_zero4(float4* p, long n4) {
    long i = (long)blockIdx.x * blockDim.x + threadIdx.x;
    if (i < n4) p[i] = make_float4(0.f, 0.f, 0.f, 0.f);
}

__global__ void copy_f4(float4* dst, const float4* src, long n4) {
    long i = (long)blockIdx.x * blockDim.x + threadIdx.x;
    if (i < n4) dst[i] = src[i];
}

// wT[s][j][k] = w[s][k][j]
__global__ void transpose_ggnn(const float* __restrict__ w, float* __restrict__ wT) {
    int t = blockIdx.x * blockDim.x + threadIdx.x;
    if (t >= NSTEPS * DD * DD) return;
    int s = t / (DD * DD);
    int rem = t - s * (DD * DD);
    int j = rem / DD, k = rem - (rem / DD) * DD;
    wT[t] = w[s * DD * DD + k * DD + j];
}

// wp[k][o][i] = w[o][i][k]   (w is [Ch, Ch, 3])
__global__ void pack_conv3(const float* __restrict__ w, float* __restrict__ wp, int Ch) {
    int t = blockIdx.x * blockDim.x + threadIdx.x;
    int total = 3 * Ch * Ch;
    if (t >= total) return;
    int k = t / (Ch * Ch);
    int rem = t - k * (Ch * Ch);
    int o = rem / Ch, i = rem - (rem / Ch) * Ch;
    wp[t] = w[(o * Ch + i) * 3 + k];
}

// c[i] = [h[i], x[i]]
__global__ void concat_kernel(const float4* __restrict__ h, const float4* __restrict__ x,
                              float4* __restrict__ c) {
    long t = (long)blockIdx.x * blockDim.x + threadIdx.x;
    if (t >= (long)NN * (DD / 4)) return;
    long i = t >> 5;               // node (32 float4 per row)
    int d = (int)(t & 31);
    c[i * (CC / 4) + d] = h[t];
    c[i * (CC / 4) + (DD / 4) + d] = x[t];
}

// ---------------- 3xBF16-split tensor-core GEMM, dist-2 A prefetch -----------
// C[M,Nc] = A[M,K] @ B[Nc,K]^T (+bias)(+acc); fp32 in gmem, split to bf16 hi/lo
// in-kernel. 128x128 tile, k16 stages, 256 threads (8 warps = 4M x 2N), warp
// tile 32x64: 2 m-frags x 8 n-frags of m16n8k16, 3 MMAs (hi*hi, lo*hi, hi*lo).
// KEY CHANGE vs R8: A tiles (per-CTA-unique -> DRAM, ~600+cyc) are prefetched
// TWO k-steps ahead via ping-pong register sets; B tiles (weights, all-CTA
// shared -> L2/L1 hit) stay at distance 1. Model: per-kstep time ~3800cyc with
// only ~500cyc of issue work => exposed A-LDG latency was the pole.
#define BM 128
#define BN 128
#define SPITCH 12
__global__ void __launch_bounds__(256, 2) gemm_bf16s(
    const float* __restrict__ A, const float* __restrict__ B,
    const float* __restrict__ bias, float* __restrict__ Cmat,
    int M, int Nc, int K, int validA, int accFlag)
{
    __shared__ __align__(16) unsigned Ah[2][BM * SPITCH];
    __shared__ __align__(16) unsigned Al[2][BM * SPITCH];
    __shared__ __align__(16) unsigned Bh[2][BN * SPITCH];
    __shared__ __align__(16) unsigned Bl[2][BN * SPITCH];
    int bm = blockIdx.x * BM;
    int bn = blockIdx.y * BN;
    int tid = threadIdx.x;
    int lane = tid & 31;
    int wid = tid >> 5;
    int warpM = wid & 3;            // 0..3 -> 32-row slab
    int warpN = wid >> 2;           // 0..1 -> 64-col slab
    int qr = lane >> 2;             // 0..7
    int qk = lane & 3;              // 0..3
    int lr = tid >> 2;              // 0..63 load row
    int lk4 = (tid & 3) * 4;        // k sub-offset (float4)
    int kp0 = lk4 >> 1;             // kpair index {0,2,4,6}

    const float4 z4 = make_float4(0.f, 0.f, 0.f, 0.f);
    const float* pa0 = A + (size_t)(bm + lr) * K + lk4;
    const float* pa1 = A + (size_t)(bm + 64 + lr) * K + lk4;
    const float* pb0 = B + (size_t)(bn + lr) * K + lk4;
    const float* pb1 = B + (size_t)(bn + 64 + lr) * K + lk4;
    bool okA0 = (bm + lr) < validA;
    bool okA1 = (bm + 64 + lr) < validA;
    bool okB0 = (bn + lr) < Nc;
    bool okB1 = (bn + 64 + lr) < Nc;

    float4 rA0[2], rA1[2];          // dist-2 ping-pong A prefetch
    float4 rB0, rB1;                // dist-1 B prefetch

    auto loadA = [&](int off, int s) {
        rA0[s] = okA0 ? *(const float4*)(pa0 + off) : z4;
        rA1[s] = okA1 ? *(const float4*)(pa1 + off) : z4;
    };
    auto loadB = [&](int off) {
        rB0 = okB0 ? *(const float4*)(pb0 + off) : z4;
        rB1 = okB1 ? *(const float4*)(pb1 + off) : z4;
    };
    auto cvt1 = [&](float4 v, unsigned* dh, unsigned* dl) {
        unsigned h0 = bfpack(v.y, v.x);
        unsigned h1 = bfpack(v.w, v.z);
        float hx = __uint_as_float(h0 << 16);
        float hy = __uint_as_float(h0 & 0xffff0000u);
        float hz = __uint_as_float(h1 << 16);
        float hw = __uint_as_float(h1 & 0xffff0000u);
        unsigned l0 = bfpack(v.y - hy, v.x - hx);
        unsigned l1 = bfpack(v.w - hw, v.z - hz);
        *(uint2*)dh = make_uint2(h0, h1);
        *(uint2*)dl = make_uint2(l0, l1);
    };
    auto storeStage = [&](int buf, int s) {
        cvt1(rA0[s], &Ah[buf][lr * SPITCH + kp0], &Al[buf][lr * SPITCH + kp0]);
        cvt1(rA1[s], &Ah[buf][(64 + lr) * SPITCH + kp0], &Al[buf][(64 + lr) * SPITCH + kp0]);
        cvt1(rB0, &Bh[buf][lr * SPITCH + kp0], &Bl[buf][lr * SPITCH + kp0]);
        cvt1(rB1, &Bh[buf][(64 + lr) * SPITCH + kp0], &Bl[buf][(64 + lr) * SPITCH + kp0]);
    };

    float acc[2][8][4];
    #pragma unroll
    for (int i = 0; i < 2; i++)
        #pragma unroll
        for (int j = 0; j < 8; j++)
            #pragma unroll
            for (int p = 0; p < 4; p++) acc[i][j][p] = 0.f;

    int ksteps = K >> 4;
    // prologue: stage 0 -> buffer 0; start stage-1 A load (distance 2 begins)
    loadA(0, 0);
    loadB(0);
    storeStage(0, 0);
    if (ksteps > 1) loadA(16, 1);
    __syncthreads();

    for (int kt = 0; kt < ksteps; kt++) {
        int cur = kt & 1;
        int nxt = cur ^ 1;
        // A for stage kt+2 into the set just freed (stage kt consumed last iter)
        if (kt + 2 < ksteps) loadA((kt + 2) * 16, kt & 1);
        // B for stage kt+1 (L2-resident; one kstep of cover suffices)
        if (kt + 1 < ksteps) loadB((kt + 1) * 16);

        const unsigned* cAh = Ah[cur];
        const unsigned* cAl = Al[cur];
        const unsigned* cBh = Bh[cur];
        const unsigned* cBl = Bl[cur];

        unsigned ahi[2][4], alo[2][4];
        #pragma unroll
        for (int mf = 0; mf < 2; mf++) {
            int r = warpM * 32 + mf * 16 + qr;
            ahi[mf][0] = cAh[r * SPITCH + qk];
            ahi[mf][1] = cAh[(r + 8) * SPITCH + qk];
            ahi[mf][2] = cAh[r * SPITCH + qk + 4];
            ahi[mf][3] = cAh[(r + 8) * SPITCH + qk + 4];
            alo[mf][0] = cAl[r * SPITCH + qk];
            alo[mf][1] = cAl[(r + 8) * SPITCH + qk];
            alo[mf][2] = cAl[r * SPITCH + qk + 4];
            alo[mf][3] = cAl[(r + 8) * SPITCH + qk + 4];
        }
        #pragma unroll
        for (int nf = 0; nf < 8; nf++) {
            int cn = warpN * 64 + nf * 8 + qr;
            unsigned bhi[2], blo[2];
            bhi[0] = cBh[cn * SPITCH + qk];
            bhi[1] = cBh[cn * SPITCH + qk + 4];
            blo[0] = cBl[cn * SPITCH + qk];
            blo[1] = cBl[cn * SPITCH + qk + 4];
            #pragma unroll
            for (int mf = 0; mf < 2; mf++) {
                mma_bf16(acc[mf][nf], ahi[mf], bhi);   // hi*hi
                mma_bf16(acc[mf][nf], alo[mf], bhi);   // lo*hi
                mma_bf16(acc[mf][nf], ahi[mf], blo);   // hi*lo
            }
        }

        // convert+store stage kt+1 (A regs loaded 2 steps ago; B this step)
        if (kt + 1 < ksteps) storeStage(nxt, (kt + 1) & 1);
        __syncthreads();
    }

    // ---- epilogue (d0,d1: row qr col 2qk..; d2,d3: row qr+8) ----
    #pragma unroll
    for (int mf = 0; mf < 2; mf++) {
        int row0 = bm + warpM * 32 + mf * 16 + qr;
        #pragma unroll
        for (int nf = 0; nf < 8; nf++) {
            int col = bn + warpN * 64 + nf * 8 + qk * 2;
            float b0 = 0.f, b1 = 0.f;
            if (bias) { b0 = bias[col]; b1 = bias[col + 1]; }
            #pragma unroll
            for (int hh = 0; hh < 2; hh++) {
                int row = row0 + hh * 8;
                if (row >= M) continue;
                float v0 = acc[mf][nf][hh * 2 + 0] + b0;
                float v1 = acc[mf][nf][hh * 2 + 1] + b1;
                float* cp = Cmat + (size_t)row * Nc + col;
                if (accFlag) {
                    float2 c0 = *(const float2*)cp;
                    v0 += c0.x; v1 += c0.y;
                }
                *(float2*)cp = make_float2(v0, v1);
            }
        }
    }
}

// ---------------- GGNN pieces ----------------
// 32 threads per edge, each does a v4 reduction of 4 channels
__global__ void scatter_kernel(const float* __restrict__ m, const int* __restrict__ ei,
                               const float* __restrict__ ew, float* __restrict__ agg) {
    long t = (long)blockIdx.x * blockDim.x + threadIdx.x;
    if (t >= (long)EE * 32) return;
    int e = (int)(t >> 5);
    int q = (int)(t & 31) * 4;
    int s = ei[e];
    int d = ei[EE + e];
    float w = ew[e];
    float4 v = *(const float4*)(m + (size_t)s * DD + q);
    float* ap = agg + (size_t)d * DD + q;
    asm volatile("red.global.add.v4.f32 [%0], {%1, %2, %3, %4};"
                 :: "l"(ap), "f"(v.x * w), "f"(v.y * w), "f"(v.z * w), "f"(v.w * w)
                 : "memory");
}

__global__ void gru_kernel(const float4* __restrict__ gx, const float4* __restrict__ gh,
                           float4* __restrict__ h) {
    long t = (long)blockIdx.x * blockDim.x + threadIdx.x;
    if (t >= (long)NN * (DD / 4)) return;
    long i = t >> 5;           // node
    int d = (int)(t & 31);     // float4 index within D
    long base = i * (3 * DD / 4);
    float4 xr = gx[base + d], xz = gx[base + 32 + d], xn = gx[base + 64 + d];
    float4 hr = gh[base + d], hz = gh[base + 32 + d], hn = gh[base + 64 + d];
    float4 hold = h[t];
    float4 outv;
    {
        float r = 1.f / (1.f + expf(-(xr.x + hr.x)));
        float z = 1.f / (1.f + expf(-(xz.x + hz.x)));
        float n = tanhf(xn.x + r * hn.x);
        outv.x = (1.f - z) * n + z * hold.x;
    }
    {
        float r = 1.f / (1.f + expf(-(xr.y + hr.y)));
        float z = 1.f / (1.f + expf(-(xz.y + hz.y)));
        float n = tanhf(xn.y + r * hn.y);
        outv.y = (1.f - z) * n + z * hold.y;
    }
    {
        float r = 1.f / (1.f + expf(-(xr.z + hr.z)));
        float z = 1.f / (1.f + expf(-(xz.z + hz.z)));
        float n = tanhf(xn.z + r * hn.z);
        outv.z = (1.f - z) * n + z * hold.z;
    }
    {
        float r = 1.f / (1.f + expf(-(xr.w + hr.w)));
        float z = 1.f / (1.f + expf(-(xz.w + hz.w)));
        float n = tanhf(xn.w + r * hn.w);
        outv.w = (1.f - z) * n + z * hold.w;
    }
    h[t] = outv;
}

// ---------------- BN stats + fused BN/ReLU/maxpool ----------------
__global__ void stats_kernel(const float* __restrict__ X, float* __restrict__ stats,
                             int Lvalid, int Lpad, int Ch, int rowsPerBlock) {
    int c = threadIdx.x;   // blockDim == Ch
    float s = 0.f, sq = 0.f;
    int base = blockIdx.x * rowsPerBlock;
    int total = GG * Lvalid;
    for (int i = 0; i < rowsPerBlock; i++) {
        int vr = base + i;
        if (vr >= total) break;
        int g = vr / Lvalid;
        int l = vr - g * Lvalid;
        float v = X[((size_t)(g * Lpad + l)) * Ch + c];
        s += v; sq += v * v;
    }
    atomicAdd(&stats[c], s);
    atomicAdd(&stats[Ch + c], sq);
}

__global__ void bn_relu_pool(const float4* __restrict__ X, float4* __restrict__ Yout,
                             const float* __restrict__ stats, const float* __restrict__ gamma,
                             const float* __restrict__ beta, int Ch, int Lpad, int Lout,
                             int win, int stride, float inv_cnt) {
    long idx = (long)blockIdx.x * blockDim.x + threadIdx.x;
    int ch4 = Ch >> 2;
    long total = (long)GG * Lout * ch4;
    if (idx >= total) return;
    int c4 = (int)(idx % ch4);
    long r = idx / ch4;
    int lp = (int)(r % Lout);
    int g = (int)(r / Lout);
    int c = c4 * 4;
    float sc[4], sh[4];
    #pragma unroll
    for (int j = 0; j < 4; j++) {
        float mean = stats[c + j] * inv_cnt;
        float var = stats[Ch + c + j] * inv_cnt - mean * mean;
        sc[j] = rsqrtf(var + 1e-5f) * gamma[c + j];
        sh[j] = beta[c + j] - mean * sc[j];
    }
    float4 mx = make_float4(0.f, 0.f, 0.f, 0.f);  // relu floor
    for (int j = 0; j < win; j++) {
        int l = lp * stride + j;
        float4 v = X[((size_t)(g * Lpad + l)) * ch4 + c4];
        mx.x = fmaxf(mx.x, v.x * sc[0] + sh[0]);
        mx.y = fmaxf(mx.y, v.y * sc[1] + sh[1]);
        mx.z = fmaxf(mx.z, v.z * sc[2] + sh[2]);
        mx.w = fmaxf(mx.w, v.w * sc[3] + sh[3]);
    }
    Yout[((size_t)(g * Lout + lp)) * ch4 + c4] = mx;
}

// ---------------- final: (Y2@Wy^T+by)*(Z2@Wz^T+bz), mean over L' ----------------
__global__ void __launch_bounds__(128) final_kernel(
    const float* __restrict__ Y2, const float* __restrict__ Z2,
    const float* __restrict__ wy, const float* __restrict__ by,
    const float* __restrict__ wz, const float* __restrict__ bz,
    float* __restrict__ out)
{
    int g = blockIdx.x, tid = threadIdx.x;
    __shared__ float swy[2 * DD];
    __shared__ float swz[2 * CC];
    __shared__ float red0[128], red1[128];
    for (int i = tid; i < 2 * DD; i += 128) swy[i] = wy[i];
    for (int i = tid; i < 2 * CC; i += 128) swz[i] = wz[i];
    __syncthreads();
    float a0 = 0.f, a1 = 0.f;
    if (tid < P2OUT) {
        const float* yr = Y2 + ((size_t)g * P2OUT + tid) * DD;
        const float* zr = Z2 + ((size_t)g * P2OUT + tid) * CC;
        float y0 = by[0], y1 = by[1], z0 = bz[0], z1 = bz[1];
        for (int d = 0; d < DD; d++) { float v = yr[d]; y0 += v * swy[d]; y1 += v * swy[DD + d]; }
        for (int d = 0; d < CC; d++) { float v = zr[d]; z0 += v * swz[d]; z1 += v * swz[CC + d]; }
        a0 = y0 * z0;
        a1 = y1 * z1;
    }
    red0[tid] = a0; red1[tid] = a1;
    __syncthreads();
    for (int s = 64; s > 0; s >>= 1) {
        if (tid < s) { red0[tid] += red0[tid + s]; red1[tid] += red1[tid + s]; }
        __syncthreads();
    }
    if (tid == 0) {
        out[g * 2 + 0] = red0[0] / (float)P2OUT;
        out[g * 2 + 1] = red1[0] / (float)P2OUT;
    }
}

// ---------------- host side ----------------
template <typename T>
static float* get_addr(T& sym) {
    void* p = nullptr;
    cudaGetSymbolAddress(&p, sym);
    return (float*)p;
}

static void gemm(const float* A, const float* B, const float* bias, float* Cm,
                 int M, int Nc, int K, int validA, int accFlag) {
    dim3 grid((M + BM - 1) / BM, (Nc + BN - 1) / BN);
    gemm_bf16s<<<grid, 256>>>(A, B, bias, Cm, M, Nc, K, validA, accFlag);
}

extern "C" void kernel_launch(void* const* d_in, const int* in_sizes, int n_in,
                              void* d_out, int out_size) {
    const float* x       = (const float*)d_in[0];
    const int*   ei      = (const int*)d_in[1];
    const float* ew      = (const float*)d_in[2];
    // d_in[3] = batch (unused: batch == arange(N)//L, so de-batchify is a reshape)
    const float* ggnn_w  = (const float*)d_in[4];
    const float* wih     = (const float*)d_in[5];
    const float* whh     = (const float*)d_in[6];
    const float* bih     = (const float*)d_in[7];
    const float* bhh     = (const float*)d_in[8];
    const float* conv1_w = (const float*)d_in[9];
    const float* conv1_b = (const float*)d_in[10];
    const float* conv2_w = (const float*)d_in[11];
    const float* conv2_b = (const float*)d_in[12];
    const float* convc1_w = (const float*)d_in[13];
    const float* convc1_b = (const float*)d_in[14];
    const float* convc2_w = (const float*)d_in[15];
    const float* convc2_b = (const float*)d_in[16];
    const float* bn1_g   = (const float*)d_in[17];
    const float* bn1_b   = (const float*)d_in[18];
    const float* bn2_g   = (const float*)d_in[19];
    const float* bn2_b   = (const float*)d_in[20];
    const float* mlpy_w  = (const float*)d_in[21];
    const float* mlpy_b  = (const float*)d_in[22];
    const float* mlpz_w  = (const float*)d_in[23];
    const float* mlpz_b  = (const float*)d_in[24];
    float* out = (float*)d_out;

    float* h    = get_addr(g_h);
    float* m    = get_addr(g_m);
    float* agg  = get_addr(g_agg);
    float* gx   = get_addr(g_gx);
    float* gh   = get_addr(g_gh);
    float* c    = get_addr(g_c);
    float* wT   = get_addr(g_wT);
    float* w1p  = get_addr(g_w1p);
    float* wc1p = get_addr(g_wc1p);
    float* cY1  = get_addr(g_convY1);
    float* pY1  = get_addr(g_poolY1);
    float* cY2  = get_addr(g_convY2);
    float* pY2  = get_addr(g_poolY2);
    float* cZ1  = get_addr(g_convZ1);
    float* pZ1  = get_addr(g_poolZ1);
    float* cZ2  = get_addr(g_convZ2);
    float* pZ2  = get_addr(g_poolZ2);
    float* st   = get_addr(g_stats);

    const long ND = (long)NN * DD;
    const long ND4 = ND / 4;

    // prep: h = x, GGNN weight transpose
    copy_f4<<<(int)((ND4 + 255) / 256), 256>>>((float4*)h, (const float4*)x, ND4);
    transpose_ggnn<<<(NSTEPS * DD * DD + 255) / 256, 256>>>(ggnn_w, wT);

    // GGNN: 6 steps (fill_zero before gemm keeps ncu's captured launch on gemm)
    for (int s = 0; s < NSTEPS; s++) {
        fill_zero4<<<(int)((ND4 + 255) / 256), 256>>>((float4*)agg, ND4);
        gemm(h, wT + s * DD * DD, nullptr, m, NN, DD, DD, NN, 0);
        scatter_kernel<<<(int)(((long)EE * 32) / 256), 256>>>(m, ei, ew, agg);
        gemm(agg, wih, bih, gx, NN, 3 * DD, DD, NN, 0);
        gemm(h, whh, bhh, gh, NN, 3 * DD, DD, NN, 0);
        gru_kernel<<<(int)((ND4 + 255) / 256), 256>>>((const float4*)gx, (const float4*)gh,
                                                      (float4*)h);
    }

    // c = [h | x]
    concat_kernel<<<(int)((ND4 + 255) / 256), 256>>>((const float4*)h, (const float4*)x,
                                                     (float4*)c);
    // conv weight repacks
    pack_conv3<<<(3 * DD * DD + 255) / 256, 256>>>(conv1_w, w1p, DD);
    pack_conv3<<<(3 * CC * CC + 255) / 256, 256>>>(convc1_w, wc1p, CC);

    // ---- Y path ----
    gemm(h,            w1p,                conv1_b, cY1, NN, DD, DD, NN,     0);
    gemm(h + DD,       w1p + DD * DD,      nullptr, cY1, NN, DD, DD, NN - 1, 1);
    gemm(h + 2 * DD,   w1p + 2 * DD * DD,  nullptr, cY1, NN, DD, DD, NN - 2, 1);
    fill_zero4<<<1, 128>>>((float4*)st, 128);
    stats_kernel<<<(GG * L1OUT + 63) / 64, DD>>>(cY1, st, L1OUT, LL, DD, 64);
    bn_relu_pool<<<(int)(((long)GG * P1OUT * DD / 4 + 255) / 256), 256>>>(
        (const float4*)cY1, (float4*)pY1, st, bn1_g, bn1_b, DD, LL, P1OUT, 3, 2,
        1.f / (GG * L1OUT));
    gemm(pY1, conv2_w, conv2_b, cY2, GG * P1OUT, DD, DD, GG * P1OUT, 0);
    fill_zero4<<<1, 128>>>((float4*)st, 128);
    stats_kernel<<<(GG * P1OUT + 63) / 64, DD>>>(cY2, st, P1OUT, P1OUT, DD, 64);
    bn_relu_pool<<<(int)(((long)GG * P2OUT * DD / 4 + 255) / 256), 256>>>(
        (const float4*)cY2, (float4*)pY2, st, bn1_g, bn1_b, DD, P1OUT, P2OUT, 2, 2,
        1.f / (GG * P1OUT));

    // ---- Z path ----
    gemm(c,            wc1p,               convc1_b, cZ1, NN, CC, CC, NN,     0);
    gemm(c + CC,       wc1p + CC * CC,     nullptr,  cZ1, NN, CC, CC, NN - 1, 1);
    gemm(c + 2 * CC,   wc1p + 2 * CC * CC, nullptr,  cZ1, NN, CC, CC, NN - 2, 1);
    fill_zero4<<<1, 128>>>((float4*)st, 128);
    stats_kernel<<<(GG * L1OUT + 63) / 64, CC>>>(cZ1, st, L1OUT, LL, CC, 64);
    bn_relu_pool<<<(int)(((long)GG * P1OUT * CC / 4 + 255) / 256), 256>>>(
        (const float4*)cZ1, (float4*)pZ1, st, bn2_g, bn2_b, CC, LL, P1OUT, 3, 2,
        1.f / (GG * L1OUT));
    gemm(pZ1, convc2_w, convc2_b, cZ2, GG * P1OUT, CC, CC, GG * P1OUT, 0);
    fill_zero4<<<1, 128>>>((float4*)st, 128);
    stats_kernel<<<(GG * P1OUT + 63) / 64, CC>>>(cZ2, st, P1OUT, P1OUT, CC, 64);
    bn_relu_pool<<<(int)(((long)GG * P2OUT * CC / 4 + 255) / 256), 256>>>(
        (const float4*)cZ2, (float4*)pZ2, st, bn2_g, bn2_b, CC, P1OUT, P2OUT, 2, 2,
        1.f / (GG * P1OUT));

    // ---- final ----
    final_kernel<<<GG, 128>>>(pY2, pZ2, mlpy_w, mlpy_b, mlpz_w, mlpz_b, out);
}

// round 15
// speedup vs baseline: 1.2351x; 1.2351x over previous
#include <cuda_runtime.h>
#include <math.h>
#include <stdint.h>

#define NN 65536
#define GG 128
#define LL 512
#define DD 128
#define EE 262144
#define NSTEPS 6
#define CC 256
#define L1OUT 510   // conv K=3 valid out length
#define P1OUT 254   // pool (3,2) out
#define P2OUT 127   // pool (2,2) out

// ---------------- scratch (device globals; no allocs allowed) ----------------
// g_h / g_c carry zero-initialized pads: fused-K conv GEMM reads up to 2 rows
// past the end (outputs for l=510,511, never consumed downstream).
__device__ float g_h[NN * DD + 768];
__device__ float g_m[NN * DD];
__device__ float g_agg[NN * DD];
__device__ float g_gx[NN * 3 * DD];
__device__ float g_gh[NN * 3 * DD];
__device__ float g_c[NN * CC + 1536];
__device__ float g_wT[NSTEPS * DD * DD];
__device__ float g_w1cat[DD * 3 * DD];       // [o][k*DD+i]
__device__ float g_wc1cat[CC * 3 * CC];      // [o][k*CC+i]
__device__ float g_convY1[NN * DD];          // [G,512,D] padded length
__device__ float g_poolY1[GG * P1OUT * DD];
__device__ float g_convY2[GG * P1OUT * DD];
__device__ float g_poolY2[GG * P2OUT * DD];
__device__ float g_convZ1[NN * CC];          // [G,512,C] padded length
__device__ float g_poolZ1[GG * P1OUT * CC];
__device__ float g_convZ2[GG * P1OUT * CC];
__device__ float g_poolZ2[GG * P2OUT * CC];
__device__ float g_stats1[512];              // Y-path stats (stream 2)
__device__ float g_stats2[512];              // Z-path stats (stream 0)

// ---------------- bf16 helpers ----------------
__device__ __forceinline__ unsigned bfpack(float hi_src, float lo_src) {
    unsigned r;
    asm("cvt.rn.bf16x2.f32 %0, %1, %2;" : "=r"(r) : "f"(hi_src), "f"(lo_src));
    return r;
}

__device__ __forceinline__ void mma_bf16(float* d, const unsigned* a, const unsigned* b) {
    asm("mma.sync.aligned.m16n8k16.row.col.f32.bf16.bf16.f32 "
        "{%0,%1,%2,%3}, {%4,%5,%6,%7}, {%8,%9}, {%0,%1,%2,%3};"
        : "+f"(d[0]), "+f"(d[1]), "+f"(d[2]), "+f"(d[3])
        : "r"(a[0]), "r"(a[1]), "r"(a[2]), "r"(a[3]), "r"(b[0]), "r"(b[1]));
}

// ---------------- small utility kernels ----------------
__global__ void fill_zero4(float4* p, long n4) {
    long i = (long)blockIdx.x * blockDim.x + threadIdx.x;
    if (i < n4) p[i] = make_float4(0.f, 0.f, 0.f, 0.f);
}

__global__ void copy_f4(float4* dst, const float4* src, long n4) {
    long i = (long)blockIdx.x * blockDim.x + threadIdx.x;
    if (i < n4) dst[i] = src[i];
}

// wT[s][j][k] = w[s][k][j]
__global__ void transpose_ggnn(const float* __restrict__ w, float* __restrict__ wT) {
    int t = blockIdx.x * blockDim.x + threadIdx.x;
    if (t >= NSTEPS * DD * DD) return;
    int s = t / (DD * DD);
    int rem = t - s * (DD * DD);
    int j = rem / DD, k = rem - (rem / DD) * DD;
    wT[t] = w[s * DD * DD + k * DD + j];
}

// wcat[o][k*Ch+i] = w[o][i][k]   (w is [Ch, Ch, 3]) -> fused-K conv weights
__global__ void pack_convcat(const float* __restrict__ w, float* __restrict__ wcat, int Ch) {
    int t = blockIdx.x * blockDim.x + threadIdx.x;
    int total = 3 * Ch * Ch;
    if (t >= total) return;
    int o = t / (3 * Ch);
    int rem = t - o * (3 * Ch);
    int k = rem / Ch, i = rem - (rem / Ch) * Ch;
    wcat[t] = w[(o * Ch + i) * 3 + k];
}

// c[i] = [h[i], x[i]]
__global__ void concat_kernel(const float4* __restrict__ h, const float4* __restrict__ x,
                              float4* __restrict__ c) {
    long t = (long)blockIdx.x * blockDim.x + threadIdx.x;
    if (t >= (long)NN * (DD / 4)) return;
    long i = t >> 5;
    int d = (int)(t & 31);
    c[i * (CC / 4) + d] = h[t];
    c[i * (CC / 4) + (DD / 4) + d] = x[t];
}

// ---------------- 3xBF16-split tensor-core GEMM (R8-proven) + lda ------------
// C[M,Nc] = A[M,K] @ B[Nc,K]^T (+bias)(+acc); fp32 in gmem, split to bf16 hi/lo
// in-kernel. A rows use stride lda (lda<K => overlapping rows, fused-K conv).
// 128x128 tile, k16 stages, 256 threads (8 warps = 4M x 2N), warp tile 32x64.
// Pipeline (R8): LDG prefetch -> LDS frags -> MMA (interleaved 3-term) ->
// cvt+STS -> one sync. Smem stride-12 rows, conflict-free.
#define BM 128
#define BN 128
#define SPITCH 12
__global__ void __launch_bounds__(256, 2) gemm_bf16s(
    const float* __restrict__ A, int lda, const float* __restrict__ B,
    const float* __restrict__ bias, float* __restrict__ Cmat,
    int M, int Nc, int K, int validA, int accFlag)
{
    __shared__ __align__(16) unsigned Ah[2][BM * SPITCH];
    __shared__ __align__(16) unsigned Al[2][BM * SPITCH];
    __shared__ __align__(16) unsigned Bh[2][BN * SPITCH];
    __shared__ __align__(16) unsigned Bl[2][BN * SPITCH];
    int bm = blockIdx.x * BM;
    int bn = blockIdx.y * BN;
    int tid = threadIdx.x;
    int lane = tid & 31;
    int wid = tid >> 5;
    int warpM = wid & 3;
    int warpN = wid >> 2;
    int qr = lane >> 2;
    int qk = lane & 3;
    int lr = tid >> 2;
    int lk4 = (tid & 3) * 4;
    int kp0 = lk4 >> 1;

    const float4 z4 = make_float4(0.f, 0.f, 0.f, 0.f);
    const float* pa0 = A + (size_t)(bm + lr) * lda + lk4;
    const float* pa1 = A + (size_t)(bm + 64 + lr) * lda + lk4;
    const float* pb0 = B + (size_t)(bn + lr) * K + lk4;
    const float* pb1 = B + (size_t)(bn + 64 + lr) * K + lk4;
    bool okA0 = (bm + lr) < validA;
    bool okA1 = (bm + 64 + lr) < validA;
    bool okB0 = (bn + lr) < Nc;
    bool okB1 = (bn + 64 + lr) < Nc;

    float4 rA0, rA1, rB0, rB1;

    auto loadRegs = [&](int off) {
        rA0 = okA0 ? *(const float4*)(pa0 + off) : z4;
        rA1 = okA1 ? *(const float4*)(pa1 + off) : z4;
        rB0 = okB0 ? *(const float4*)(pb0 + off) : z4;
        rB1 = okB1 ? *(const float4*)(pb1 + off) : z4;
    };
    auto cvt1 = [&](float4 v, unsigned* dh, unsigned* dl) {
        unsigned h0 = bfpack(v.y, v.x);
        unsigned h1 = bfpack(v.w, v.z);
        float hx = __uint_as_float(h0 << 16);
        float hy = __uint_as_float(h0 & 0xffff0000u);
        float hz = __uint_as_float(h1 << 16);
        float hw = __uint_as_float(h1 & 0xffff0000u);
        unsigned l0 = bfpack(v.y - hy, v.x - hx);
        unsigned l1 = bfpack(v.w - hw, v.z - hz);
        *(uint2*)dh = make_uint2(h0, h1);
        *(uint2*)dl = make_uint2(l0, l1);
    };

    float acc[2][8][4];
    #pragma unroll
    for (int i = 0; i < 2; i++)
        #pragma unroll
        for (int j = 0; j < 8; j++)
            #pragma unroll
            for (int p = 0; p < 4; p++) acc[i][j][p] = 0.f;

    int ksteps = K >> 4;
    loadRegs(0);
    cvt1(rA0, &Ah[0][lr * SPITCH + kp0], &Al[0][lr * SPITCH + kp0]);
    cvt1(rA1, &Ah[0][(64 + lr) * SPITCH + kp0], &Al[0][(64 + lr) * SPITCH + kp0]);
    cvt1(rB0, &Bh[0][lr * SPITCH + kp0], &Bl[0][lr * SPITCH + kp0]);
    cvt1(rB1, &Bh[0][(64 + lr) * SPITCH + kp0], &Bl[0][(64 + lr) * SPITCH + kp0]);
    __syncthreads();

    for (int kt = 0; kt < ksteps; kt++) {
        int cur = kt & 1;
        int nxt = cur ^ 1;
        bool more = (kt + 1 < ksteps);
        if (more) loadRegs((kt + 1) * 16);

        const unsigned* cAh = Ah[cur];
        const unsigned* cAl = Al[cur];
        const unsigned* cBh = Bh[cur];
        const unsigned* cBl = Bl[cur];

        unsigned ahi[2][4], alo[2][4];
        #pragma unroll
        for (int mf = 0; mf < 2; mf++) {
            int r = warpM * 32 + mf * 16 + qr;
            ahi[mf][0] = cAh[r * SPITCH + qk];
            ahi[mf][1] = cAh[(r + 8) * SPITCH + qk];
            ahi[mf][2] = cAh[r * SPITCH + qk + 4];
            ahi[mf][3] = cAh[(r + 8) * SPITCH + qk + 4];
            alo[mf][0] = cAl[r * SPITCH + qk];
            alo[mf][1] = cAl[(r + 8) * SPITCH + qk];
            alo[mf][2] = cAl[r * SPITCH + qk + 4];
            alo[mf][3] = cAl[(r + 8) * SPITCH + qk + 4];
        }
        #pragma unroll
        for (int nf = 0; nf < 8; nf++) {
            int cn = warpN * 64 + nf * 8 + qr;
            unsigned bhi[2], blo[2];
            bhi[0] = cBh[cn * SPITCH + qk];
            bhi[1] = cBh[cn * SPITCH + qk + 4];
            blo[0] = cBl[cn * SPITCH + qk];
            blo[1] = cBl[cn * SPITCH + qk + 4];
            #pragma unroll
            for (int mf = 0; mf < 2; mf++) {
                mma_bf16(acc[mf][nf], ahi[mf], bhi);   // hi*hi
                mma_bf16(acc[mf][nf], alo[mf], bhi);   // lo*hi
                mma_bf16(acc[mf][nf], ahi[mf], blo);   // hi*lo
            }
        }

        if (more) {
            cvt1(rA0, &Ah[nxt][lr * SPITCH + kp0], &Al[nxt][lr * SPITCH + kp0]);
            cvt1(rA1, &Ah[nxt][(64 + lr) * SPITCH + kp0], &Al[nxt][(64 + lr) * SPITCH + kp0]);
            cvt1(rB0, &Bh[nxt][lr * SPITCH + kp0], &Bl[nxt][lr * SPITCH + kp0]);
            cvt1(rB1, &Bh[nxt][(64 + lr) * SPITCH + kp0], &Bl[nxt][(64 + lr) * SPITCH + kp0]);
        }
        __syncthreads();
    }

    #pragma unroll
    for (int mf = 0; mf < 2; mf++) {
        int row0 = bm + warpM * 32 + mf * 16 + qr;
        #pragma unroll
        for (int nf = 0; nf < 8; nf++) {
            int col = bn + warpN * 64 + nf * 8 + qk * 2;
            float b0 = 0.f, b1 = 0.f;
            if (bias) { b0 = bias[col]; b1 = bias[col + 1]; }
            #pragma unroll
            for (int hh = 0; hh < 2; hh++) {
                int row = row0 + hh * 8;
                if (row >= M) continue;
                float v0 = acc[mf][nf][hh * 2 + 0] + b0;
                float v1 = acc[mf][nf][hh * 2 + 1] + b1;
                float* cp = Cmat + (size_t)row * Nc + col;
                if (accFlag) {
                    float2 c0 = *(const float2*)cp;
                    v0 += c0.x; v1 += c0.y;
                }
                *(float2*)cp = make_float2(v0, v1);
            }
        }
    }
}

// ---------------- GGNN pieces ----------------
__global__ void scatter_kernel(const float* __restrict__ m, const int* __restrict__ ei,
                               const float* __restrict__ ew, float* __restrict__ agg) {
    long t = (long)blockIdx.x * blockDim.x + threadIdx.x;
    if (t >= (long)EE * 32) return;
    int e = (int)(t >> 5);
    int q = (int)(t & 31) * 4;
    int s = ei[e];
    int d = ei[EE + e];
    float w = ew[e];
    float4 v = *(const float4*)(m + (size_t)s * DD + q);
    float* ap = agg + (size_t)d * DD + q;
    asm volatile("red.global.add.v4.f32 [%0], {%1, %2, %3, %4};"
                 :: "l"(ap), "f"(v.x * w), "f"(v.y * w), "f"(v.z * w), "f"(v.w * w)
                 : "memory");
}

__global__ void gru_kernel(const float4* __restrict__ gx, const float4* __restrict__ gh,
                           float4* __restrict__ h) {
    long t = (long)blockIdx.x * blockDim.x + threadIdx.x;
    if (t >= (long)NN * (DD / 4)) return;
    long i = t >> 5;
    int d = (int)(t & 31);
    long base = i * (3 * DD / 4);
    float4 xr = gx[base + d], xz = gx[base + 32 + d], xn = gx[base + 64 + d];
    float4 hr = gh[base + d], hz = gh[base + 32 + d], hn = gh[base + 64 + d];
    float4 hold = h[t];
    float4 outv;
    {
        float r = 1.f / (1.f + expf(-(xr.x + hr.x)));
        float z = 1.f / (1.f + expf(-(xz.x + hz.x)));
        float n = tanhf(xn.x + r * hn.x);
        outv.x = (1.f - z) * n + z * hold.x;
    }
    {
        float r = 1.f / (1.f + expf(-(xr.y + hr.y)));
        float z = 1.f / (1.f + expf(-(xz.y + hz.y)));
        float n = tanhf(xn.y + r * hn.y);
        outv.y = (1.f - z) * n + z * hold.y;
    }
    {
        float r = 1.f / (1.f + expf(-(xr.z + hr.z)));
        float z = 1.f / (1.f + expf(-(xz.z + hz.z)));
        float n = tanhf(xn.z + r * hn.z);
        outv.z = (1.f - z) * n + z * hold.z;
    }
    {
        float r = 1.f / (1.f + expf(-(xr.w + hr.w)));
        float z = 1.f / (1.f + expf(-(xz.w + hz.w)));
        float n = tanhf(xn.w + r * hn.w);
        outv.w = (1.f - z) * n + z * hold.w;
    }
    h[t] = outv;
}

// ---------------- BN stats + fused BN/ReLU/maxpool ----------------
__global__ void stats_kernel(const float* __restrict__ X, float* __restrict__ stats,
                             int Lvalid, int Lpad, int Ch, int rowsPerBlock) {
    int c = threadIdx.x;
    float s = 0.f, sq = 0.f;
    int base = blockIdx.x * rowsPerBlock;
    int total = GG * Lvalid;
    for (int i = 0; i < rowsPerBlock; i++) {
        int vr = base + i;
        if (vr >= total) break;
        int g = vr / Lvalid;
        int l = vr - g * Lvalid;
        float v = X[((size_t)(g * Lpad + l)) * Ch + c];
        s += v; sq += v * v;
    }
    atomicAdd(&stats[c], s);
    atomicAdd(&stats[Ch + c], sq);
}

__global__ void bn_relu_pool(const float4* __restrict__ X, float4* __restrict__ Yout,
                             const float* __restrict__ stats, const float* __restrict__ gamma,
                             const float* __restrict__ beta, int Ch, int Lpad, int Lout,
                             int win, int stride, float inv_cnt) {
    long idx = (long)blockIdx.x * blockDim.x + threadIdx.x;
    int ch4 = Ch >> 2;
    long total = (long)GG * Lout * ch4;
    if (idx >= total) return;
    int c4 = (int)(idx % ch4);
    long r = idx / ch4;
    int lp = (int)(r % Lout);
    int g = (int)(r / Lout);
    int c = c4 * 4;
    float sc[4], sh[4];
    #pragma unroll
    for (int j = 0; j < 4; j++) {
        float mean = stats[c + j] * inv_cnt;
        float var = stats[Ch + c + j] * inv_cnt - mean * mean;
        sc[j] = rsqrtf(var + 1e-5f) * gamma[c + j];
        sh[j] = beta[c + j] - mean * sc[j];
    }
    float4 mx = make_float4(0.f, 0.f, 0.f, 0.f);
    for (int j = 0; j < win; j++) {
        int l = lp * stride + j;
        float4 v = X[((size_t)(g * Lpad + l)) * ch4 + c4];
        mx.x = fmaxf(mx.x, v.x * sc[0] + sh[0]);
        mx.y = fmaxf(mx.y, v.y * sc[1] + sh[1]);
        mx.z = fmaxf(mx.z, v.z * sc[2] + sh[2]);
        mx.w = fmaxf(mx.w, v.w * sc[3] + sh[3]);
    }
    Yout[((size_t)(g * Lout + lp)) * ch4 + c4] = mx;
}

// ---------------- final ----------------
__global__ void __launch_bounds__(128) final_kernel(
    const float* __restrict__ Y2, const float* __restrict__ Z2,
    const float* __restrict__ wy, const float* __restrict__ by,
    const float* __restrict__ wz, const float* __restrict__ bz,
    float* __restrict__ out)
{
    int g = blockIdx.x, tid = threadIdx.x;
    __shared__ float swy[2 * DD];
    __shared__ float swz[2 * CC];
    __shared__ float red0[128], red1[128];
    for (int i = tid; i < 2 * DD; i += 128) swy[i] = wy[i];
    for (int i = tid; i < 2 * CC; i += 128) swz[i] = wz[i];
    __syncthreads();
    float a0 = 0.f, a1 = 0.f;
    if (tid < P2OUT) {
        const float* yr = Y2 + ((size_t)g * P2OUT + tid) * DD;
        const float* zr = Z2 + ((size_t)g * P2OUT + tid) * CC;
        float y0 = by[0], y1 = by[1], z0 = bz[0], z1 = bz[1];
        for (int d = 0; d < DD; d++) { float v = yr[d]; y0 += v * swy[d]; y1 += v * swy[DD + d]; }
        for (int d = 0; d < CC; d++) { float v = zr[d]; z0 += v * swz[d]; z1 += v * swz[CC + d]; }
        a0 = y0 * z0;
        a1 = y1 * z1;
    }
    red0[tid] = a0; red1[tid] = a1;
    __syncthreads();
    for (int s = 64; s > 0; s >>= 1) {
        if (tid < s) { red0[tid] += red0[tid + s]; red1[tid] += red1[tid + s]; }
        __syncthreads();
    }
    if (tid == 0) {
        out[g * 2 + 0] = red0[0] / (float)P2OUT;
        out[g * 2 + 1] = red1[0] / (float)P2OUT;
    }
}

// ---------------- host side ----------------
template <typename T>
static float* get_addr(T& sym) {
    void* p = nullptr;
    cudaGetSymbolAddress(&p, sym);
    return (float*)p;
}

static void gemm_s(cudaStream_t st, const float* A, int lda, const float* B,
                   const float* bias, float* Cm, int M, int Nc, int K,
                   int validA, int accFlag) {
    dim3 grid((M + BM - 1) / BM, (Nc + BN - 1) / BN);
    gemm_bf16s<<<grid, 256, 0, st>>>(A, lda, B, bias, Cm, M, Nc, K, validA, accFlag);
}

extern "C" void kernel_launch(void* const* d_in, const int* in_sizes, int n_in,
                              void* d_out, int out_size) {
    const float* x       = (const float*)d_in[0];
    const int*   ei      = (const int*)d_in[1];
    const float* ew      = (const float*)d_in[2];
    // d_in[3] = batch (unused: batch == arange(N)//L -> reshape)
    const float* ggnn_w  = (const float*)d_in[4];
    const float* wih     = (const float*)d_in[5];
    const float* whh     = (const float*)d_in[6];
    const float* bih     = (const float*)d_in[7];
    const float* bhh     = (const float*)d_in[8];
    const float* conv1_w = (const float*)d_in[9];
    const float* conv1_b = (const float*)d_in[10];
    const float* conv2_w = (const float*)d_in[11];
    const float* conv2_b = (const float*)d_in[12];
    const float* convc1_w = (const float*)d_in[13];
    const float* convc1_b = (const float*)d_in[14];
    const float* convc2_w = (const float*)d_in[15];
    const float* convc2_b = (const float*)d_in[16];
    const float* bn1_g   = (const float*)d_in[17];
    const float* bn1_b   = (const float*)d_in[18];
    const float* bn2_g   = (const float*)d_in[19];
    const float* bn2_b   = (const float*)d_in[20];
    const float* mlpy_w  = (const float*)d_in[21];
    const float* mlpy_b  = (const float*)d_in[22];
    const float* mlpz_w  = (const float*)d_in[23];
    const float* mlpz_b  = (const float*)d_in[24];
    float* out = (float*)d_out;

    float* h     = get_addr(g_h);
    float* m     = get_addr(g_m);
    float* agg   = get_addr(g_agg);
    float* gx    = get_addr(g_gx);
    float* gh    = get_addr(g_gh);
    float* c     = get_addr(g_c);
    float* wT    = get_addr(g_wT);
    float* w1cat = get_addr(g_w1cat);
    float* wc1cat = get_addr(g_wc1cat);
    float* cY1   = get_addr(g_convY1);
    float* pY1   = get_addr(g_poolY1);
    float* cY2   = get_addr(g_convY2);
    float* pY2   = get_addr(g_poolY2);
    float* cZ1   = get_addr(g_convZ1);
    float* pZ1   = get_addr(g_poolZ1);
    float* cZ2   = get_addr(g_convZ2);
    float* pZ2   = get_addr(g_poolZ2);
    float* st1   = get_addr(g_stats1);
    float* st2   = get_addr(g_stats2);

    // second stream + fork/join events (created once; no device memory)
    static cudaStream_t s2 = nullptr;
    static cudaEvent_t evA = nullptr, evB = nullptr, evC = nullptr, evD = nullptr;
    if (!s2) {
        cudaStreamCreateWithFlags(&s2, cudaStreamNonBlocking);
        cudaEventCreateWithFlags(&evA, cudaEventDisableTiming);
        cudaEventCreateWithFlags(&evB, cudaEventDisableTiming);
        cudaEventCreateWithFlags(&evC, cudaEventDisableTiming);
        cudaEventCreateWithFlags(&evD, cudaEventDisableTiming);
    }
    cudaStream_t s0 = 0;

    const long ND = (long)NN * DD;
    const long ND4 = ND / 4;

    // prep (launches 0-1), then GGNN loop with first gemm at capture slot 3
    copy_f4<<<(int)((ND4 + 255) / 256), 256>>>((float4*)h, (const float4*)x, ND4);
    transpose_ggnn<<<(NSTEPS * DD * DD + 255) / 256, 256>>>(ggnn_w, wT);

    // GGNN: 6 steps. gh-gemm runs on s2 concurrently with fill/m-gemm/scatter.
    for (int s = 0; s < NSTEPS; s++) {
        fill_zero4<<<(int)((ND4 + 255) / 256), 256>>>((float4*)agg, ND4);
        cudaEventRecord(evA, s0);
        cudaStreamWaitEvent(s2, evA, 0);
        gemm_s(s2, h, DD, whh, bhh, gh, NN, 3 * DD, DD, NN, 0);
        cudaEventRecord(evB, s2);
        gemm_s(s0, h, DD, wT + s * DD * DD, nullptr, m, NN, DD, DD, NN, 0);
        scatter_kernel<<<(int)(((long)EE * 32) / 256), 256>>>(m, ei, ew, agg);
        gemm_s(s0, agg, DD, wih, bih, gx, NN, 3 * DD, DD, NN, 0);
        cudaStreamWaitEvent(s0, evB, 0);
        gru_kernel<<<(int)((ND4 + 255) / 256), 256>>>((const float4*)gx, (const float4*)gh,
                                                      (float4*)h);
    }

    // c = [h | x]
    concat_kernel<<<(int)((ND4 + 255) / 256), 256>>>((const float4*)h, (const float4*)x,
                                                     (float4*)c);

    // fork: Y path on s2, Z path on s0
    cudaEventRecord(evC, s0);
    cudaStreamWaitEvent(s2, evC, 0);

    // ---- Y path (stream s2) ----
    pack_convcat<<<(3 * DD * DD + 255) / 256, 256, 0, s2>>>(conv1_w, w1cat, DD);
    gemm_s(s2, h, DD, w1cat, conv1_b, cY1, NN, DD, 3 * DD, NN, 0);   // fused K=384
    fill_zero4<<<1, 128, 0, s2>>>((float4*)st1, 128);
    stats_kernel<<<(GG * L1OUT + 63) / 64, DD, 0, s2>>>(cY1, st1, L1OUT, LL, DD, 64);
    bn_relu_pool<<<(int)(((long)GG * P1OUT * DD / 4 + 255) / 256), 256, 0, s2>>>(
        (const float4*)cY1, (float4*)pY1, st1, bn1_g, bn1_b, DD, LL, P1OUT, 3, 2,
        1.f / (GG * L1OUT));
    gemm_s(s2, pY1, DD, conv2_w, conv2_b, cY2, GG * P1OUT, DD, DD, GG * P1OUT, 0);
    fill_zero4<<<1, 128, 0, s2>>>((float4*)st1, 128);
    stats_kernel<<<(GG * P1OUT + 63) / 64, DD, 0, s2>>>(cY2, st1, P1OUT, P1OUT, DD, 64);
    bn_relu_pool<<<(int)(((long)GG * P2OUT * DD / 4 + 255) / 256), 256, 0, s2>>>(
        (const float4*)cY2, (float4*)pY2, st1, bn1_g, bn1_b, DD, P1OUT, P2OUT, 2, 2,
        1.f / (GG * P1OUT));
    cudaEventRecord(evD, s2);

    // ---- Z path (stream 0) ----
    pack_convcat<<<(3 * CC * CC + 255) / 256, 256>>>(convc1_w, wc1cat, CC);
    gemm_s(s0, c, CC, wc1cat, convc1_b, cZ1, NN, CC, 3 * CC, NN, 0);  // fused K=768
    fill_zero4<<<1, 128>>>((float4*)st2, 128);
    stats_kernel<<<(GG * L1OUT + 63) / 64, CC>>>(cZ1, st2, L1OUT, LL, CC, 64);
    bn_relu_pool<<<(int)(((long)GG * P1OUT * CC / 4 + 255) / 256), 256>>>(
        (const float4*)cZ1, (float4*)pZ1, st2, bn2_g, bn2_b, CC, LL, P1OUT, 3, 2,
        1.f / (GG * L1OUT));
    gemm_s(s0, pZ1, CC, convc2_w, convc2_b, cZ2, GG * P1OUT, CC, CC, GG * P1OUT, 0);
    fill_zero4<<<1, 128>>>((float4*)st2, 128);
    stats_kernel<<<(GG * P1OUT + 63) / 64, CC>>>(cZ2, st2, P1OUT, P1OUT, CC, 64);
    bn_relu_pool<<<(int)(((long)GG * P2OUT * CC / 4 + 255) / 256), 256>>>(
        (const float4*)cZ2, (float4*)pZ2, st2, bn2_g, bn2_b, CC, P1OUT, P2OUT, 2, 2,
        1.f / (GG * P1OUT));

    // join + final
    cudaStreamWaitEvent(s0, evD, 0);
    final_kernel<<<GG, 128>>>(pY2, pZ2, mlpy_w, mlpy_b, mlpz_w, mlpz_b, out);
}

// round 16
// speedup vs baseline: 1.2527x; 1.0143x over previous
#include <cuda_runtime.h>
#include <math.h>
#include <stdint.h>

#define NN 65536
#define GG 128
#define LL 512
#define DD 128
#define EE 262144
#define NSTEPS 6
#define CC 256
#define L1OUT 510   // conv K=3 valid out length
#define P1OUT 254   // pool (3,2) out
#define P2OUT 127   // pool (2,2) out

// ---------------- scratch (device globals; no allocs allowed) ----------------
// g_h / g_c carry zero-initialized pads: fused-K conv GEMM reads up to 2 rows
// past the end (outputs for l=510,511, never consumed downstream).
__device__ float g_h[NN * DD + 768];
__device__ float g_m[NN * DD];
__device__ float g_agg[NN * DD];
__device__ float g_gx[NN * 3 * DD];
__device__ float g_gh[NN * 3 * DD];
__device__ float g_c[NN * CC + 1536];
__device__ float g_wT[NSTEPS * DD * DD];
__device__ float g_w1cat[DD * 3 * DD];       // [o][k*DD+i]
__device__ float g_wc1cat[CC * 3 * CC];      // [o][k*CC+i]
__device__ float g_convY1[NN * DD];          // [G,512,D] padded length
__device__ float g_poolY1[GG * P1OUT * DD];
__device__ float g_convY2[GG * P1OUT * DD];
__device__ float g_poolY2[GG * P2OUT * DD];
__device__ float g_convZ1[NN * CC];          // [G,512,C] padded length
__device__ float g_poolZ1[GG * P1OUT * CC];
__device__ float g_convZ2[GG * P1OUT * CC];
__device__ float g_poolZ2[GG * P2OUT * CC];
__device__ float g_stats1[512];              // Y-path stats (stream 2)
__device__ float g_stats2[512];              // Z-path stats (stream 0)

// ---------------- bf16 helpers ----------------
__device__ __forceinline__ unsigned bfpack(float hi_src, float lo_src) {
    unsigned r;
    asm("cvt.rn.bf16x2.f32 %0, %1, %2;" : "=r"(r) : "f"(hi_src), "f"(lo_src));
    return r;
}

__device__ __forceinline__ void mma_bf16(float* d, const unsigned* a, const unsigned* b) {
    asm("mma.sync.aligned.m16n8k16.row.col.f32.bf16.bf16.f32 "
        "{%0,%1,%2,%3}, {%4,%5,%6,%7}, {%8,%9}, {%0,%1,%2,%3};"
        : "+f"(d[0]), "+f"(d[1]), "+f"(d[2]), "+f"(d[3])
        : "r"(a[0]), "r"(a[1]), "r"(a[2]), "r"(a[3]), "r"(b[0]), "r"(b[1]));
}

// ---------------- small utility kernels ----------------
__global__ void fill_zero4(float4* p, long n4) {
    long i = (long)blockIdx.x * blockDim.x + threadIdx.x;
    if (i < n4) p[i] = make_float4(0.f, 0.f, 0.f, 0.f);
}

__global__ void copy_f4(float4* dst, const float4* src, long n4) {
    long i = (long)blockIdx.x * blockDim.x + threadIdx.x;
    if (i < n4) dst[i] = src[i];
}

// wT[s][j][k] = w[s][k][j]
__global__ void transpose_ggnn(const float* __restrict__ w, float* __restrict__ wT) {
    int t = blockIdx.x * blockDim.x + threadIdx.x;
    if (t >= NSTEPS * DD * DD) return;
    int s = t / (DD * DD);
    int rem = t - s * (DD * DD);
    int j = rem / DD, k = rem - (rem / DD) * DD;
    wT[t] = w[s * DD * DD + k * DD + j];
}

// wcat[o][k*Ch+i] = w[o][i][k]   (w is [Ch, Ch, 3]) -> fused-K conv weights
__global__ void pack_convcat(const float* __restrict__ w, float* __restrict__ wcat, int Ch) {
    int t = blockIdx.x * blockDim.x + threadIdx.x;
    int total = 3 * Ch * Ch;
    if (t >= total) return;
    int o = t / (3 * Ch);
    int rem = t - o * (3 * Ch);
    int k = rem / Ch, i = rem - (rem / Ch) * Ch;
    wcat[t] = w[(o * Ch + i) * 3 + k];
}

// c[i] = [h[i], x[i]]
__global__ void concat_kernel(const float4* __restrict__ h, const float4* __restrict__ x,
                              float4* __restrict__ c) {
    long t = (long)blockIdx.x * blockDim.x + threadIdx.x;
    if (t >= (long)NN * (DD / 4)) return;
    long i = t >> 5;
    int d = (int)(t & 31);
    c[i * (CC / 4) + d] = h[t];
    c[i * (CC / 4) + (DD / 4) + d] = x[t];
}

// ---------------- 3xBF16-split tensor-core GEMM (R8 core) + lda + fused stats
// C[M,Nc] = A[M,K] @ B[Nc,K]^T (+bias)(+acc); fp32 in gmem, split to bf16 hi/lo
// in-kernel. A rows use stride lda (lda<K => overlapping rows, fused-K conv).
// If stats != nullptr (single-pass conv gemms only): epilogue accumulates
// per-column sum into stats[col] and sumsq into stats[Nc+col], masking rows
// with (row % sLpad) >= sLvalid (the padded conv output rows).
#define BM 128
#define BN 128
#define SPITCH 12
__global__ void __launch_bounds__(256, 2) gemm_bf16s(
    const float* __restrict__ A, int lda, const float* __restrict__ B,
    const float* __restrict__ bias, float* __restrict__ Cmat,
    int M, int Nc, int K, int validA, int accFlag,
    float* __restrict__ stats, int sLpad, int sLvalid)
{
    __shared__ __align__(16) unsigned Ah[2][BM * SPITCH];
    __shared__ __align__(16) unsigned Al[2][BM * SPITCH];
    __shared__ __align__(16) unsigned Bh[2][BN * SPITCH];
    __shared__ __align__(16) unsigned Bl[2][BN * SPITCH];
    int bm = blockIdx.x * BM;
    int bn = blockIdx.y * BN;
    int tid = threadIdx.x;
    int lane = tid & 31;
    int wid = tid >> 5;
    int warpM = wid & 3;
    int warpN = wid >> 2;
    int qr = lane >> 2;
    int qk = lane & 3;
    int lr = tid >> 2;
    int lk4 = (tid & 3) * 4;
    int kp0 = lk4 >> 1;

    const float4 z4 = make_float4(0.f, 0.f, 0.f, 0.f);
    const float* pa0 = A + (size_t)(bm + lr) * lda + lk4;
    const float* pa1 = A + (size_t)(bm + 64 + lr) * lda + lk4;
    const float* pb0 = B + (size_t)(bn + lr) * K + lk4;
    const float* pb1 = B + (size_t)(bn + 64 + lr) * K + lk4;
    bool okA0 = (bm + lr) < validA;
    bool okA1 = (bm + 64 + lr) < validA;
    bool okB0 = (bn + lr) < Nc;
    bool okB1 = (bn + 64 + lr) < Nc;

    float4 rA0, rA1, rB0, rB1;

    auto loadRegs = [&](int off) {
        rA0 = okA0 ? *(const float4*)(pa0 + off) : z4;
        rA1 = okA1 ? *(const float4*)(pa1 + off) : z4;
        rB0 = okB0 ? *(const float4*)(pb0 + off) : z4;
        rB1 = okB1 ? *(const float4*)(pb1 + off) : z4;
    };
    auto cvt1 = [&](float4 v, unsigned* dh, unsigned* dl) {
        unsigned h0 = bfpack(v.y, v.x);
        unsigned h1 = bfpack(v.w, v.z);
        float hx = __uint_as_float(h0 << 16);
        float hy = __uint_as_float(h0 & 0xffff0000u);
        float hz = __uint_as_float(h1 << 16);
        float hw = __uint_as_float(h1 & 0xffff0000u);
        unsigned l0 = bfpack(v.y - hy, v.x - hx);
        unsigned l1 = bfpack(v.w - hw, v.z - hz);
        *(uint2*)dh = make_uint2(h0, h1);
        *(uint2*)dl = make_uint2(l0, l1);
    };

    float acc[2][8][4];
    #pragma unroll
    for (int i = 0; i < 2; i++)
        #pragma unroll
        for (int j = 0; j < 8; j++)
            #pragma unroll
            for (int p = 0; p < 4; p++) acc[i][j][p] = 0.f;

    int ksteps = K >> 4;
    loadRegs(0);
    cvt1(rA0, &Ah[0][lr * SPITCH + kp0], &Al[0][lr * SPITCH + kp0]);
    cvt1(rA1, &Ah[0][(64 + lr) * SPITCH + kp0], &Al[0][(64 + lr) * SPITCH + kp0]);
    cvt1(rB0, &Bh[0][lr * SPITCH + kp0], &Bl[0][lr * SPITCH + kp0]);
    cvt1(rB1, &Bh[0][(64 + lr) * SPITCH + kp0], &Bl[0][(64 + lr) * SPITCH + kp0]);
    __syncthreads();

    for (int kt = 0; kt < ksteps; kt++) {
        int cur = kt & 1;
        int nxt = cur ^ 1;
        bool more = (kt + 1 < ksteps);
        if (more) loadRegs((kt + 1) * 16);

        const unsigned* cAh = Ah[cur];
        const unsigned* cAl = Al[cur];
        const unsigned* cBh = Bh[cur];
        const unsigned* cBl = Bl[cur];

        unsigned ahi[2][4], alo[2][4];
        #pragma unroll
        for (int mf = 0; mf < 2; mf++) {
            int r = warpM * 32 + mf * 16 + qr;
            ahi[mf][0] = cAh[r * SPITCH + qk];
            ahi[mf][1] = cAh[(r + 8) * SPITCH + qk];
            ahi[mf][2] = cAh[r * SPITCH + qk + 4];
            ahi[mf][3] = cAh[(r + 8) * SPITCH + qk + 4];
            alo[mf][0] = cAl[r * SPITCH + qk];
            alo[mf][1] = cAl[(r + 8) * SPITCH + qk];
            alo[mf][2] = cAl[r * SPITCH + qk + 4];
            alo[mf][3] = cAl[(r + 8) * SPITCH + qk + 4];
        }
        #pragma unroll
        for (int nf = 0; nf < 8; nf++) {
            int cn = warpN * 64 + nf * 8 + qr;
            unsigned bhi[2], blo[2];
            bhi[0] = cBh[cn * SPITCH + qk];
            bhi[1] = cBh[cn * SPITCH + qk + 4];
            blo[0] = cBl[cn * SPITCH + qk];
            blo[1] = cBl[cn * SPITCH + qk + 4];
            #pragma unroll
            for (int mf = 0; mf < 2; mf++) {
                mma_bf16(acc[mf][nf], ahi[mf], bhi);   // hi*hi
                mma_bf16(acc[mf][nf], alo[mf], bhi);   // lo*hi
                mma_bf16(acc[mf][nf], ahi[mf], blo);   // hi*lo
            }
        }

        if (more) {
            cvt1(rA0, &Ah[nxt][lr * SPITCH + kp0], &Al[nxt][lr * SPITCH + kp0]);
            cvt1(rA1, &Ah[nxt][(64 + lr) * SPITCH + kp0], &Al[nxt][(64 + lr) * SPITCH + kp0]);
            cvt1(rB0, &Bh[nxt][lr * SPITCH + kp0], &Bl[nxt][lr * SPITCH + kp0]);
            cvt1(rB1, &Bh[nxt][(64 + lr) * SPITCH + kp0], &Bl[nxt][(64 + lr) * SPITCH + kp0]);
        }
        __syncthreads();
    }

    // ---- epilogue (+ optional fused BN stats) ----
    bool doStats = (stats != nullptr);
    #pragma unroll
    for (int nf = 0; nf < 8; nf++) {
        int col = bn + warpN * 64 + nf * 8 + qk * 2;
        float b0 = 0.f, b1 = 0.f;
        if (bias) { b0 = bias[col]; b1 = bias[col + 1]; }
        float s0a = 0.f, s1a = 0.f, q0a = 0.f, q1a = 0.f;
        #pragma unroll
        for (int mf = 0; mf < 2; mf++) {
            int row0 = bm + warpM * 32 + mf * 16 + qr;
            #pragma unroll
            for (int hh = 0; hh < 2; hh++) {
                int row = row0 + hh * 8;
                if (row >= M) continue;
                float v0 = acc[mf][nf][hh * 2 + 0] + b0;
                float v1 = acc[mf][nf][hh * 2 + 1] + b1;
                float* cp = Cmat + (size_t)row * Nc + col;
                if (accFlag) {
                    float2 c0 = *(const float2*)cp;
                    v0 += c0.x; v1 += c0.y;
                }
                *(float2*)cp = make_float2(v0, v1);
                if (doStats && (row % sLpad) < sLvalid) {
                    s0a += v0; q0a += v0 * v0;
                    s1a += v1; q1a += v1 * v1;
                }
            }
        }
        if (doStats) {
            #pragma unroll
            for (int mk = 4; mk <= 16; mk <<= 1) {
                s0a += __shfl_xor_sync(0xffffffffu, s0a, mk);
                q0a += __shfl_xor_sync(0xffffffffu, q0a, mk);
                s1a += __shfl_xor_sync(0xffffffffu, s1a, mk);
                q1a += __shfl_xor_sync(0xffffffffu, q1a, mk);
            }
            if (qr == 0) {
                atomicAdd(&stats[col], s0a);
                atomicAdd(&stats[col + 1], s1a);
                atomicAdd(&stats[Nc + col], q0a);
                atomicAdd(&stats[Nc + col + 1], q1a);
            }
        }
    }
}

// ---------------- GGNN pieces ----------------
__global__ void scatter_kernel(const float* __restrict__ m, const int* __restrict__ ei,
                               const float* __restrict__ ew, float* __restrict__ agg) {
    long t = (long)blockIdx.x * blockDim.x + threadIdx.x;
    if (t >= (long)EE * 32) return;
    int e = (int)(t >> 5);
    int q = (int)(t & 31) * 4;
    int s = ei[e];
    int d = ei[EE + e];
    float w = ew[e];
    float4 v = *(const float4*)(m + (size_t)s * DD + q);
    float* ap = agg + (size_t)d * DD + q;
    asm volatile("red.global.add.v4.f32 [%0], {%1, %2, %3, %4};"
                 :: "l"(ap), "f"(v.x * w), "f"(v.y * w), "f"(v.z * w), "f"(v.w * w)
                 : "memory");
}

__global__ void gru_kernel(const float4* __restrict__ gx, const float4* __restrict__ gh,
                           float4* __restrict__ h) {
    long t = (long)blockIdx.x * blockDim.x + threadIdx.x;
    if (t >= (long)NN * (DD / 4)) return;
    long i = t >> 5;
    int d = (int)(t & 31);
    long base = i * (3 * DD / 4);
    float4 xr = gx[base + d], xz = gx[base + 32 + d], xn = gx[base + 64 + d];
    float4 hr = gh[base + d], hz = gh[base + 32 + d], hn = gh[base + 64 + d];
    float4 hold = h[t];
    float4 outv;
    {
        float r = 1.f / (1.f + expf(-(xr.x + hr.x)));
        float z = 1.f / (1.f + expf(-(xz.x + hz.x)));
        float n = tanhf(xn.x + r * hn.x);
        outv.x = (1.f - z) * n + z * hold.x;
    }
    {
        float r = 1.f / (1.f + expf(-(xr.y + hr.y)));
        float z = 1.f / (1.f + expf(-(xz.y + hz.y)));
        float n = tanhf(xn.y + r * hn.y);
        outv.y = (1.f - z) * n + z * hold.y;
    }
    {
        float r = 1.f / (1.f + expf(-(xr.z + hr.z)));
        float z = 1.f / (1.f + expf(-(xz.z + hz.z)));
        float n = tanhf(xn.z + r * hn.z);
        outv.z = (1.f - z) * n + z * hold.z;
    }
    {
        float r = 1.f / (1.f + expf(-(xr.w + hr.w)));
        float z = 1.f / (1.f + expf(-(xz.w + hz.w)));
        float n = tanhf(xn.w + r * hn.w);
        outv.w = (1.f - z) * n + z * hold.w;
    }
    h[t] = outv;
}

// ---------------- fused BN/ReLU/maxpool ----------------
__global__ void bn_relu_pool(const float4* __restrict__ X, float4* __restrict__ Yout,
                             const float* __restrict__ stats, const float* __restrict__ gamma,
                             const float* __restrict__ beta, int Ch, int Lpad, int Lout,
                             int win, int stride, float inv_cnt) {
    long idx = (long)blockIdx.x * blockDim.x + threadIdx.x;
    int ch4 = Ch >> 2;
    long total = (long)GG * Lout * ch4;
    if (idx >= total) return;
    int c4 = (int)(idx % ch4);
    long r = idx / ch4;
    int lp = (int)(r % Lout);
    int g = (int)(r / Lout);
    int c = c4 * 4;
    float sc[4], sh[4];
    #pragma unroll
    for (int j = 0; j < 4; j++) {
        float mean = stats[c + j] * inv_cnt;
        float var = stats[Ch + c + j] * inv_cnt - mean * mean;
        sc[j] = rsqrtf(var + 1e-5f) * gamma[c + j];
        sh[j] = beta[c + j] - mean * sc[j];
    }
    float4 mx = make_float4(0.f, 0.f, 0.f, 0.f);
    for (int j = 0; j < win; j++) {
        int l = lp * stride + j;
        float4 v = X[((size_t)(g * Lpad + l)) * ch4 + c4];
        mx.x = fmaxf(mx.x, v.x * sc[0] + sh[0]);
        mx.y = fmaxf(mx.y, v.y * sc[1] + sh[1]);
        mx.z = fmaxf(mx.z, v.z * sc[2] + sh[2]);
        mx.w = fmaxf(mx.w, v.w * sc[3] + sh[3]);
    }
    Yout[((size_t)(g * Lout + lp)) * ch4 + c4] = mx;
}

// ---------------- final ----------------
__global__ void __launch_bounds__(128) final_kernel(
    const float* __restrict__ Y2, const float* __restrict__ Z2,
    const float* __restrict__ wy, const float* __restrict__ by,
    const float* __restrict__ wz, const float* __restrict__ bz,
    float* __restrict__ out)
{
    int g = blockIdx.x, tid = threadIdx.x;
    __shared__ float swy[2 * DD];
    __shared__ float swz[2 * CC];
    __shared__ float red0[128], red1[128];
    for (int i = tid; i < 2 * DD; i += 128) swy[i] = wy[i];
    for (int i = tid; i < 2 * CC; i += 128) swz[i] = wz[i];
    __syncthreads();
    float a0 = 0.f, a1 = 0.f;
    if (tid < P2OUT) {
        const float* yr = Y2 + ((size_t)g * P2OUT + tid) * DD;
        const float* zr = Z2 + ((size_t)g * P2OUT + tid) * CC;
        float y0 = by[0], y1 = by[1], z0 = bz[0], z1 = bz[1];
        for (int d = 0; d < DD; d++) { float v = yr[d]; y0 += v * swy[d]; y1 += v * swy[DD + d]; }
        for (int d = 0; d < CC; d++) { float v = zr[d]; z0 += v * swz[d]; z1 += v * swz[CC + d]; }
        a0 = y0 * z0;
        a1 = y1 * z1;
    }
    red0[tid] = a0; red1[tid] = a1;
    __syncthreads();
    for (int s = 64; s > 0; s >>= 1) {
        if (tid < s) { red0[tid] += red0[tid + s]; red1[tid] += red1[tid + s]; }
        __syncthreads();
    }
    if (tid == 0) {
        out[g * 2 + 0] = red0[0] / (float)P2OUT;
        out[g * 2 + 1] = red1[0] / (float)P2OUT;
    }
}

// ---------------- host side ----------------
template <typename T>
static float* get_addr(T& sym) {
    void* p = nullptr;
    cudaGetSymbolAddress(&p, sym);
    return (float*)p;
}

static void gemm_s(cudaStream_t st, const float* A, int lda, const float* B,
                   const float* bias, float* Cm, int M, int Nc, int K,
                   int validA, int accFlag,
                   float* stats = nullptr, int sLpad = 1, int sLvalid = 1) {
    dim3 grid((M + BM - 1) / BM, (Nc + BN - 1) / BN);
    gemm_bf16s<<<grid, 256, 0, st>>>(A, lda, B, bias, Cm, M, Nc, K, validA, accFlag,
                                     stats, sLpad, sLvalid);
}

extern "C" void kernel_launch(void* const* d_in, const int* in_sizes, int n_in,
                              void* d_out, int out_size) {
    const float* x       = (const float*)d_in[0];
    const int*   ei      = (const int*)d_in[1];
    const float* ew      = (const float*)d_in[2];
    // d_in[3] = batch (unused: batch == arange(N)//L -> reshape)
    const float* ggnn_w  = (const float*)d_in[4];
    const float* wih     = (const float*)d_in[5];
    const float* whh     = (const float*)d_in[6];
    const float* bih     = (const float*)d_in[7];
    const float* bhh     = (const float*)d_in[8];
    const float* conv1_w = (const float*)d_in[9];
    const float* conv1_b = (const float*)d_in[10];
    const float* conv2_w = (const float*)d_in[11];
    const float* conv2_b = (const float*)d_in[12];
    const float* convc1_w = (const float*)d_in[13];
    const float* convc1_b = (const float*)d_in[14];
    const float* convc2_w = (const float*)d_in[15];
    const float* convc2_b = (const float*)d_in[16];
    const float* bn1_g   = (const float*)d_in[17];
    const float* bn1_b   = (const float*)d_in[18];
    const float* bn2_g   = (const float*)d_in[19];
    const float* bn2_b   = (const float*)d_in[20];
    const float* mlpy_w  = (const float*)d_in[21];
    const float* mlpy_b  = (const float*)d_in[22];
    const float* mlpz_w  = (const float*)d_in[23];
    const float* mlpz_b  = (const float*)d_in[24];
    float* out = (float*)d_out;

    float* h     = get_addr(g_h);
    float* m     = get_addr(g_m);
    float* agg   = get_addr(g_agg);
    float* gx    = get_addr(g_gx);
    float* gh    = get_addr(g_gh);
    float* c     = get_addr(g_c);
    float* wT    = get_addr(g_wT);
    float* w1cat = get_addr(g_w1cat);
    float* wc1cat = get_addr(g_wc1cat);
    float* cY1   = get_addr(g_convY1);
    float* pY1   = get_addr(g_poolY1);
    float* cY2   = get_addr(g_convY2);
    float* pY2   = get_addr(g_poolY2);
    float* cZ1   = get_addr(g_convZ1);
    float* pZ1   = get_addr(g_poolZ1);
    float* cZ2   = get_addr(g_convZ2);
    float* pZ2   = get_addr(g_poolZ2);
    float* st1   = get_addr(g_stats1);
    float* st2   = get_addr(g_stats2);

    // second stream + fork/join events (created once; no device memory)
    static cudaStream_t s2 = nullptr;
    static cudaEvent_t evA = nullptr, evB = nullptr, evC = nullptr, evD = nullptr,
                       evF = nullptr;
    if (!s2) {
        cudaStreamCreateWithFlags(&s2, cudaStreamNonBlocking);
        cudaEventCreateWithFlags(&evA, cudaEventDisableTiming);
        cudaEventCreateWithFlags(&evB, cudaEventDisableTiming);
        cudaEventCreateWithFlags(&evC, cudaEventDisableTiming);
        cudaEventCreateWithFlags(&evD, cudaEventDisableTiming);
        cudaEventCreateWithFlags(&evF, cudaEventDisableTiming);
    }
    cudaStream_t s0 = 0;

    const long ND = (long)NN * DD;
    const long ND4 = ND / 4;

    // prep
    copy_f4<<<(int)((ND4 + 255) / 256), 256>>>((float4*)h, (const float4*)x, ND4);
    transpose_ggnn<<<(NSTEPS * DD * DD + 255) / 256, 256>>>(ggnn_w, wT);

    // GGNN: 6 steps. s2 runs fill(agg) then gh-gemm, overlapping s0's
    // m-gemm/scatter/gx chain. Hazards: s2 waits evA (recorded after prev gru,
    // which follows gx = last agg reader); s0's scatter waits evF (fill done);
    // s0's gru waits evB (gh done).
    for (int s = 0; s < NSTEPS; s++) {
        cudaEventRecord(evA, s0);
        cudaStreamWaitEvent(s2, evA, 0);
        fill_zero4<<<(int)((ND4 + 255) / 256), 256, 0, s2>>>((float4*)agg, ND4);
        cudaEventRecord(evF, s2);
        gemm_s(s2, h, DD, whh, bhh, gh, NN, 3 * DD, DD, NN, 0);
        cudaEventRecord(evB, s2);
        gemm_s(s0, h, DD, wT + s * DD * DD, nullptr, m, NN, DD, DD, NN, 0);
        cudaStreamWaitEvent(s0, evF, 0);
        scatter_kernel<<<(int)(((long)EE * 32) / 256), 256>>>(m, ei, ew, agg);
        gemm_s(s0, agg, DD, wih, bih, gx, NN, 3 * DD, DD, NN, 0);
        cudaStreamWaitEvent(s0, evB, 0);
        gru_kernel<<<(int)((ND4 + 255) / 256), 256>>>((const float4*)gx, (const float4*)gh,
                                                      (float4*)h);
    }

    // c = [h | x]
    concat_kernel<<<(int)((ND4 + 255) / 256), 256>>>((const float4*)h, (const float4*)x,
                                                     (float4*)c);

    // fork: Y path on s2, Z path on s0
    cudaEventRecord(evC, s0);
    cudaStreamWaitEvent(s2, evC, 0);

    // ---- Y path (stream s2) ----
    pack_convcat<<<(3 * DD * DD + 255) / 256, 256, 0, s2>>>(conv1_w, w1cat, DD);
    fill_zero4<<<1, 128, 0, s2>>>((float4*)st1, 128);
    gemm_s(s2, h, DD, w1cat, conv1_b, cY1, NN, DD, 3 * DD, NN, 0, st1, LL, L1OUT);
    bn_relu_pool<<<(int)(((long)GG * P1OUT * DD / 4 + 255) / 256), 256, 0, s2>>>(
        (const float4*)cY1, (float4*)pY1, st1, bn1_g, bn1_b, DD, LL, P1OUT, 3, 2,
        1.f / (GG * L1OUT));
    fill_zero4<<<1, 128, 0, s2>>>((float4*)st1, 128);
    gemm_s(s2, pY1, DD, conv2_w, conv2_b, cY2, GG * P1OUT, DD, DD, GG * P1OUT, 0,
           st1, P1OUT, P1OUT);
    bn_relu_pool<<<(int)(((long)GG * P2OUT * DD / 4 + 255) / 256), 256, 0, s2>>>(
        (const float4*)cY2, (float4*)pY2, st1, bn1_g, bn1_b, DD, P1OUT, P2OUT, 2, 2,
        1.f / (GG * P1OUT));
    cudaEventRecord(evD, s2);

    // ---- Z path (stream 0) ----
    pack_convcat<<<(3 * CC * CC + 255) / 256, 256>>>(convc1_w, wc1cat, CC);
    fill_zero4<<<1, 128>>>((float4*)st2, 128);
    gemm_s(s0, c, CC, wc1cat, convc1_b, cZ1, NN, CC, 3 * CC, NN, 0, st2, LL, L1OUT);
    bn_relu_pool<<<(int)(((long)GG * P1OUT * CC / 4 + 255) / 256), 256>>>(
        (const float4*)cZ1, (float4*)pZ1, st2, bn2_g, bn2_b, CC, LL, P1OUT, 3, 2,
        1.f / (GG * L1OUT));
    fill_zero4<<<1, 128>>>((float4*)st2, 128);
    gemm_s(s0, pZ1, CC, convc2_w, convc2_b, cZ2, GG * P1OUT, CC, CC, GG * P1OUT, 0,
           st2, P1OUT, P1OUT);
    bn_relu_pool<<<(int)(((long)GG * P2OUT * CC / 4 + 255) / 256), 256>>>(
        (const float4*)cZ2, (float4*)pZ2, st2, bn2_g, bn2_b, CC, P1OUT, P2OUT, 2, 2,
        1.f / (GG * P1OUT));

    // join + final
    cudaStreamWaitEvent(s0, evD, 0);
    final_kernel<<<GG, 128>>>(pY2, pZ2, mlpy_w, mlpy_b, mlpz_w, mlpz_b, out);
}